// round 1
// baseline (speedup 1.0000x reference)
#include <cuda_runtime.h>
#include <cstdint>

// Problem constants
#define B_SZ 8192
#define H_SZ 1024
#define K_TOT 2048      // 1024 (x/Wih) + 1024 (hx/Whh)
#define N_TOT 4096      // 4 gates * H

// GEMM tiling
#define BM 128
#define BN 128
#define BK 16
#define TM 8
#define TN 8
// threads per block = (BM/TM)*(BN/TN) = 256

// 128 MB scratch for gates = [X|Hx] @ [Wih;Whh]^T (no bias; added in epilogue)
__device__ float g_gates[(size_t)B_SZ * N_TOT];

// ---------------------------------------------------------------------------
// GEMM: C[M=8192, N=4096] = A[M, K=2048] * W[N, K=2048]^T
// A = [X | Hx] virtually concatenated along K; W = [Wih ; Whh] likewise.
// All source matrices are row-major with row stride 1024 floats.
// ---------------------------------------------------------------------------
__global__ __launch_bounds__(256) void gemm_gates_kernel(
    const float* __restrict__ X,
    const float* __restrict__ Hx,
    const float* __restrict__ Wih,
    const float* __restrict__ Whh)
{
    __shared__ float As[BK][BM];
    __shared__ float Bs[BK][BN];

    const int tid = threadIdx.x;
    const int m0 = blockIdx.y * BM;
    const int n0 = blockIdx.x * BN;

    // global-load indices: each thread loads 2 float4 for A and 2 for B
    const int lr = tid >> 2;          // 0..63
    const int lc = (tid & 3) * 4;     // 0,4,8,12

    // compute indices
    const int tx = tid & 15;          // n direction
    const int ty = tid >> 4;          // m direction
    const int mm = ty * TM;
    const int nn = tx * TN;

    float acc[TM][TN];
#pragma unroll
    for (int i = 0; i < TM; i++)
#pragma unroll
        for (int j = 0; j < TN; j++) acc[i][j] = 0.0f;

    float4 a0, a1, b0, b1;

    auto load_tile = [&](int kt) {
        const int kb = kt * BK;
        const float* Abase = (kb < H_SZ) ? (X + kb)  : (Hx  + (kb - H_SZ));
        const float* Bbase = (kb < H_SZ) ? (Wih + kb) : (Whh + (kb - H_SZ));
        a0 = *(const float4*)(Abase + (size_t)(m0 + lr)      * H_SZ + lc);
        a1 = *(const float4*)(Abase + (size_t)(m0 + lr + 64) * H_SZ + lc);
        b0 = *(const float4*)(Bbase + (size_t)(n0 + lr)      * H_SZ + lc);
        b1 = *(const float4*)(Bbase + (size_t)(n0 + lr + 64) * H_SZ + lc);
    };

    const int NT = K_TOT / BK;   // 128 k-tiles
    load_tile(0);

    for (int kt = 0; kt < NT; ++kt) {
        __syncthreads();  // previous compute done before smem overwrite
        // store staged regs (transposed) into smem
        As[lc + 0][lr] = a0.x; As[lc + 1][lr] = a0.y; As[lc + 2][lr] = a0.z; As[lc + 3][lr] = a0.w;
        As[lc + 0][lr + 64] = a1.x; As[lc + 1][lr + 64] = a1.y; As[lc + 2][lr + 64] = a1.z; As[lc + 3][lr + 64] = a1.w;
        Bs[lc + 0][lr] = b0.x; Bs[lc + 1][lr] = b0.y; Bs[lc + 2][lr] = b0.z; Bs[lc + 3][lr] = b0.w;
        Bs[lc + 0][lr + 64] = b1.x; Bs[lc + 1][lr + 64] = b1.y; Bs[lc + 2][lr + 64] = b1.z; Bs[lc + 3][lr + 64] = b1.w;
        __syncthreads();

        if (kt + 1 < NT) load_tile(kt + 1);  // LDGs in flight during compute

#pragma unroll
        for (int k = 0; k < BK; k++) {
            float ar[TM], br[TN];
            *(float4*)&ar[0] = *(const float4*)&As[k][mm];
            *(float4*)&ar[4] = *(const float4*)&As[k][mm + 4];
            *(float4*)&br[0] = *(const float4*)&Bs[k][nn];
            *(float4*)&br[4] = *(const float4*)&Bs[k][nn + 4];
#pragma unroll
            for (int i = 0; i < TM; i++)
#pragma unroll
                for (int j = 0; j < TN; j++)
                    acc[i][j] = fmaf(ar[i], br[j], acc[i][j]);
        }
    }

    // write back
#pragma unroll
    for (int i = 0; i < TM; i++) {
        float* crow = g_gates + (size_t)(m0 + mm + i) * N_TOT + (n0 + nn);
        float4 v0 = make_float4(acc[i][0], acc[i][1], acc[i][2], acc[i][3]);
        float4 v1 = make_float4(acc[i][4], acc[i][5], acc[i][6], acc[i][7]);
        *(float4*)(crow)     = v0;
        *(float4*)(crow + 4) = v1;
    }
}

// ---------------------------------------------------------------------------
// Epilogue: per batch row — bias add, 4 gate layernorms + activations,
// cell update, cy layernorm, hy. One block (256 threads) per row; each thread
// owns 4 consecutive h-elements per chunk (float4).
// ---------------------------------------------------------------------------
__device__ __forceinline__ float sigmoidf_(float x) { return 1.0f / (1.0f + __expf(-x)); }

// block-wide mean/rstd over 1024 elems; shm must hold >= 18 floats
__device__ __forceinline__ void block_ln_stats(float s, float ss, float* shm,
                                               float& mean, float& rstd)
{
    const int lane = threadIdx.x & 31;
    const int warp = threadIdx.x >> 5;
#pragma unroll
    for (int o = 16; o > 0; o >>= 1) {
        s  += __shfl_xor_sync(0xffffffff, s,  o);
        ss += __shfl_xor_sync(0xffffffff, ss, o);
    }
    if (lane == 0) { shm[warp] = s; shm[8 + warp] = ss; }
    __syncthreads();
    if (threadIdx.x == 0) {
        float ts = 0.f, tss = 0.f;
#pragma unroll
        for (int i = 0; i < 8; i++) { ts += shm[i]; tss += shm[8 + i]; }
        shm[16] = ts; shm[17] = tss;
    }
    __syncthreads();
    const float ts = shm[16], tss = shm[17];
    mean = ts * (1.0f / 1024.0f);
    float var = tss * (1.0f / 1024.0f) - mean * mean;
    rstd = rsqrtf(var + 1e-5f);
    __syncthreads();  // safe to reuse shm afterwards
}

__global__ __launch_bounds__(256) void lstm_epilogue_kernel(
    const float* __restrict__ cx,
    const float* __restrict__ bias_ih, const float* __restrict__ bias_hh,
    const float* __restrict__ ln_i_g,  const float* __restrict__ ln_i_b,
    const float* __restrict__ ln_f_g,  const float* __restrict__ ln_f_b,
    const float* __restrict__ ln_c_g,  const float* __restrict__ ln_c_b,
    const float* __restrict__ ln_cy_g, const float* __restrict__ ln_cy_b,
    const float* __restrict__ ln_o_g,  const float* __restrict__ ln_o_b,
    float* __restrict__ hy_out, float* __restrict__ cy_out)
{
    __shared__ float shm[18];
    const int b   = blockIdx.x;
    const int tid = threadIdx.x;
    const int h4  = tid * 4;   // base h-index for this thread's float4

    const float* grow = g_gates + (size_t)b * N_TOT;

    // ------- load the 4 gate chunks (+ bias) for this thread's 4 elems -------
    float4 gv[4];
#pragma unroll
    for (int q = 0; q < 4; q++) {
        const int col = q * H_SZ + h4;
        float4 v  = *(const float4*)(grow + col);
        float4 bi = *(const float4*)(bias_ih + col);
        float4 bh = *(const float4*)(bias_hh + col);
        v.x += bi.x + bh.x; v.y += bi.y + bh.y;
        v.z += bi.z + bh.z; v.w += bi.w + bh.w;
        gv[q] = v;
    }

    // ------- per-chunk layernorm + activation -------
    const float* gam[4] = { ln_i_g, ln_f_g, ln_c_g, ln_o_g };
    const float* bet[4] = { ln_i_b, ln_f_b, ln_c_b, ln_o_b };
    float4 act[4];
#pragma unroll
    for (int q = 0; q < 4; q++) {
        float4 v = gv[q];
        float s  = v.x + v.y + v.z + v.w;
        float ss = v.x * v.x + v.y * v.y + v.z * v.z + v.w * v.w;
        float mean, rstd;
        block_ln_stats(s, ss, shm, mean, rstd);
        float4 g4 = *(const float4*)(gam[q] + h4);
        float4 b4 = *(const float4*)(bet[q] + h4);
        float4 n;
        n.x = (v.x - mean) * rstd * g4.x + b4.x;
        n.y = (v.y - mean) * rstd * g4.y + b4.y;
        n.z = (v.z - mean) * rstd * g4.z + b4.z;
        n.w = (v.w - mean) * rstd * g4.w + b4.w;
        if (q == 2) {  // c gate -> tanh
            n.x = tanhf(n.x); n.y = tanhf(n.y); n.z = tanhf(n.z); n.w = tanhf(n.w);
        } else {       // i, f, o -> sigmoid
            n.x = sigmoidf_(n.x); n.y = sigmoidf_(n.y);
            n.z = sigmoidf_(n.z); n.w = sigmoidf_(n.w);
        }
        act[q] = n;
    }

    // ------- cell update: t = f*cx + i*c, then LN -> cy; hy = o*tanh(cy) -------
    float4 cxv = *(const float4*)(cx + (size_t)b * H_SZ + h4);
    float4 t;
    t.x = act[1].x * cxv.x + act[0].x * act[2].x;
    t.y = act[1].y * cxv.y + act[0].y * act[2].y;
    t.z = act[1].z * cxv.z + act[0].z * act[2].z;
    t.w = act[1].w * cxv.w + act[0].w * act[2].w;

    {
        float s  = t.x + t.y + t.z + t.w;
        float ss = t.x * t.x + t.y * t.y + t.z * t.z + t.w * t.w;
        float mean, rstd;
        block_ln_stats(s, ss, shm, mean, rstd);
        float4 g4 = *(const float4*)(ln_cy_g + h4);
        float4 b4 = *(const float4*)(ln_cy_b + h4);
        float4 cyv;
        cyv.x = (t.x - mean) * rstd * g4.x + b4.x;
        cyv.y = (t.y - mean) * rstd * g4.y + b4.y;
        cyv.z = (t.z - mean) * rstd * g4.z + b4.z;
        cyv.w = (t.w - mean) * rstd * g4.w + b4.w;

        float4 hyv;
        hyv.x = act[3].x * tanhf(cyv.x);
        hyv.y = act[3].y * tanhf(cyv.y);
        hyv.z = act[3].z * tanhf(cyv.z);
        hyv.w = act[3].w * tanhf(cyv.w);

        *(float4*)(cy_out + (size_t)b * H_SZ + h4) = cyv;
        *(float4*)(hy_out + (size_t)b * H_SZ + h4) = hyv;
    }
}

// ---------------------------------------------------------------------------
// Launch
// ---------------------------------------------------------------------------
extern "C" void kernel_launch(void* const* d_in, const int* in_sizes, int n_in,
                              void* d_out, int out_size)
{
    const float* x        = (const float*)d_in[0];
    const float* hx       = (const float*)d_in[1];
    const float* cx       = (const float*)d_in[2];
    const float* wih      = (const float*)d_in[3];
    const float* whh      = (const float*)d_in[4];
    const float* bias_ih  = (const float*)d_in[5];
    const float* bias_hh  = (const float*)d_in[6];
    const float* ln_i_g   = (const float*)d_in[7];
    const float* ln_i_b   = (const float*)d_in[8];
    const float* ln_f_g   = (const float*)d_in[9];
    const float* ln_f_b   = (const float*)d_in[10];
    const float* ln_c_g   = (const float*)d_in[11];  // ln_cx_*
    const float* ln_c_b   = (const float*)d_in[12];
    const float* ln_cy_g  = (const float*)d_in[13];
    const float* ln_cy_b  = (const float*)d_in[14];
    const float* ln_o_g   = (const float*)d_in[15];
    const float* ln_o_b   = (const float*)d_in[16];

    float* out = (float*)d_out;
    float* hy  = out;                           // [8192, 1024]
    float* cy  = out + (size_t)B_SZ * H_SZ;     // [8192, 1024]

    dim3 ggrid(N_TOT / BN, B_SZ / BM);  // (32, 64)
    gemm_gates_kernel<<<ggrid, 256>>>(x, hx, wih, whh);

    lstm_epilogue_kernel<<<B_SZ, 256>>>(cx, bias_ih, bias_hh,
                                        ln_i_g, ln_i_b, ln_f_g, ln_f_b,
                                        ln_c_g, ln_c_b, ln_cy_g, ln_cy_b,
                                        ln_o_g, ln_o_b, hy, cy);
}

// round 3
// speedup vs baseline: 1.9823x; 1.9823x over previous
#include <cuda_runtime.h>
#include <cuda_bf16.h>
#include <cstdint>

// ---------------------------------------------------------------------------
// Problem constants
// ---------------------------------------------------------------------------
#define B_SZ 8192
#define H_SZ 1024
#define K_TOT 2048       // 1024 (x/Wih) + 1024 (hx/Whh)
#define N_TOT 4096       // 4 gates * H
#define K_EXT 6144       // 3 * K_TOT (hi*hi | lo*hi | hi*lo split-GEMM)

// GEMM tiling
#define BM 256
#define BN 128
#define BK 32
#define ITERS (K_EXT / BK)    // 192
#define NSTAGE 3

// smem: padded rows of 40 bf16 (80 B) for conflict-free ldmatrix
#define ROW_PITCH 40
#define A_BYTES (BM * ROW_PITCH * 2)   // 20480
#define B_BYTES (BN * ROW_PITCH * 2)   // 10240
#define STAGE_BYTES (A_BYTES + B_BYTES)
#define GEMM_SMEM (NSTAGE * STAGE_BYTES)   // 92160

// ---------------------------------------------------------------------------
// Scratch (device globals; no allocations allowed)
// ---------------------------------------------------------------------------
__device__ __nv_bfloat16 g_Aext[(size_t)B_SZ * K_EXT];   // [Ahi | Alo | Ahi]
__device__ __nv_bfloat16 g_Bext[(size_t)N_TOT * K_EXT];  // [Bhi | Bhi | Blo]
__device__ float         g_gates[(size_t)B_SZ * N_TOT];

// ---------------------------------------------------------------------------
// PTX helpers (sm_100 base ISA only: cp.async / ldmatrix / mma.sync)
// ---------------------------------------------------------------------------
__device__ __forceinline__ uint32_t smem_u32(const void* p) {
    uint32_t r;
    asm("{ .reg .u64 t; cvta.to.shared.u64 t, %1; cvt.u32.u64 %0, t; }"
        : "=r"(r) : "l"(p));
    return r;
}
__device__ __forceinline__ void cp16(uint32_t dst, const void* src) {
    asm volatile("cp.async.cg.shared.global [%0], [%1], 16;" :: "r"(dst), "l"(src));
}
__device__ __forceinline__ void cp_commit() {
    asm volatile("cp.async.commit_group;" ::: "memory");
}
template <int N> __device__ __forceinline__ void cp_wait() {
    asm volatile("cp.async.wait_group %0;" :: "n"(N) : "memory");
}
__device__ __forceinline__ void ldm_x4(uint32_t& r0, uint32_t& r1,
                                       uint32_t& r2, uint32_t& r3, uint32_t addr) {
    asm volatile("ldmatrix.sync.aligned.m8n8.x4.shared.b16 {%0,%1,%2,%3}, [%4];"
                 : "=r"(r0), "=r"(r1), "=r"(r2), "=r"(r3) : "r"(addr));
}
__device__ __forceinline__ void mma_bf16(float* c, const uint32_t* a,
                                         uint32_t b0, uint32_t b1) {
    asm volatile(
        "mma.sync.aligned.m16n8k16.row.col.f32.bf16.bf16.f32 "
        "{%0,%1,%2,%3}, {%4,%5,%6,%7}, {%8,%9}, {%0,%1,%2,%3};"
        : "+f"(c[0]), "+f"(c[1]), "+f"(c[2]), "+f"(c[3])
        : "r"(a[0]), "r"(a[1]), "r"(a[2]), "r"(a[3]), "r"(b0), "r"(b1));
}

// ---------------------------------------------------------------------------
// Conversion: fp32 -> bf16 hi/lo extended-K scratch
// A = [x|hx] rows 8192, K=2048; A_ext row = [hi(0:2048) | lo | hi]
// B = [Wih|Whh] rows 4096;      B_ext row = [hi | hi | lo]
// ---------------------------------------------------------------------------
__device__ __forceinline__ void split4(const float4& v, __nv_bfloat162& h01,
                                       __nv_bfloat162& h23, __nv_bfloat162& l01,
                                       __nv_bfloat162& l23) {
    float vv[4] = {v.x, v.y, v.z, v.w};
    __nv_bfloat16 h[4], l[4];
#pragma unroll
    for (int j = 0; j < 4; j++) {
        h[j] = __float2bfloat16_rn(vv[j]);
        l[j] = __float2bfloat16_rn(vv[j] - __bfloat162float(h[j]));
    }
    h01 = __halves2bfloat162(h[0], h[1]);
    h23 = __halves2bfloat162(h[2], h[3]);
    l01 = __halves2bfloat162(l[0], l[1]);
    l23 = __halves2bfloat162(l[2], l[3]);
}

__global__ __launch_bounds__(256) void convert_A_kernel(
    const float* __restrict__ x, const float* __restrict__ hx)
{
    int idx = blockIdx.x * 256 + threadIdx.x;      // one float4 per thread
    int row = idx >> 9;                            // 512 float4 per K_TOT row
    int c4  = (idx & 511) * 4;
    const float* src = (c4 < H_SZ) ? (x  + (size_t)row * H_SZ + c4)
                                   : (hx + (size_t)row * H_SZ + (c4 - H_SZ));
    float4 v = *(const float4*)src;
    __nv_bfloat162 h01, h23, l01, l23;
    split4(v, h01, h23, l01, l23);
    __nv_bfloat16* dst = g_Aext + (size_t)row * K_EXT;
    *(__nv_bfloat162*)(dst + c4)              = h01;
    *(__nv_bfloat162*)(dst + c4 + 2)          = h23;
    *(__nv_bfloat162*)(dst + K_TOT + c4)      = l01;   // seg1: Alo
    *(__nv_bfloat162*)(dst + K_TOT + c4 + 2)  = l23;
    *(__nv_bfloat162*)(dst + 2*K_TOT + c4)    = h01;   // seg2: Ahi
    *(__nv_bfloat162*)(dst + 2*K_TOT + c4 + 2)= h23;
}

__global__ __launch_bounds__(256) void convert_B_kernel(
    const float* __restrict__ wih, const float* __restrict__ whh)
{
    int idx = blockIdx.x * 256 + threadIdx.x;
    int row = idx >> 9;
    int c4  = (idx & 511) * 4;
    const float* src = (c4 < H_SZ) ? (wih + (size_t)row * H_SZ + c4)
                                   : (whh + (size_t)row * H_SZ + (c4 - H_SZ));
    float4 v = *(const float4*)src;
    __nv_bfloat162 h01, h23, l01, l23;
    split4(v, h01, h23, l01, l23);
    __nv_bfloat16* dst = g_Bext + (size_t)row * K_EXT;
    *(__nv_bfloat162*)(dst + c4)              = h01;
    *(__nv_bfloat162*)(dst + c4 + 2)          = h23;
    *(__nv_bfloat162*)(dst + K_TOT + c4)      = h01;   // seg1: Bhi
    *(__nv_bfloat162*)(dst + K_TOT + c4 + 2)  = h23;
    *(__nv_bfloat162*)(dst + 2*K_TOT + c4)    = l01;   // seg2: Blo
    *(__nv_bfloat162*)(dst + 2*K_TOT + c4 + 2)= l23;
}

// ---------------------------------------------------------------------------
// GEMM: gates[8192,4096] = A_ext[8192,6144] @ B_ext[4096,6144]^T  (bf16 mma.sync)
// CTA 256x128, BK=32, 512 threads (16 warps, 8x2), warp tile 32x64, 3 stages.
// ---------------------------------------------------------------------------
__global__ __launch_bounds__(512) void gemm_mma_kernel()
{
    extern __shared__ char smem[];
    const uint32_t sbase = smem_u32(smem);

    const int tid  = threadIdx.x;
    const int lane = tid & 31;
    const int wid  = tid >> 5;
    const int warp_m = wid >> 1;      // 0..7
    const int warp_n = wid & 1;       // 0..1
    const int m_warp = warp_m * 32;
    const int n_warp = warp_n * 64;

    const int m0 = blockIdx.y * BM;
    const int n0 = blockIdx.x * BN;

    // global-load indexing (16B chunks; row-pitch 40 elems in smem)
    // A: 1024 chunks (256 rows x 4), 2 per thread; B: 512 chunks, 1 per thread
    const int ac0 = tid * 2, ac1 = tid * 2 + 1;
    const int ar0 = ac0 >> 2, ak0 = ac0 & 3;
    const int ar1 = ac1 >> 2, ak1 = ac1 & 3;
    const int br  = tid >> 2, bk = tid & 3;

    auto issue_stage = [&](int it, int s) {
        const uint32_t As = sbase + (uint32_t)s * STAGE_BYTES;
        const uint32_t Bs = As + A_BYTES;
        const int kb = it * BK;
        cp16(As + (uint32_t)(ar0 * 80 + ak0 * 16),
             g_Aext + (size_t)(m0 + ar0) * K_EXT + kb + ak0 * 8);
        cp16(As + (uint32_t)(ar1 * 80 + ak1 * 16),
             g_Aext + (size_t)(m0 + ar1) * K_EXT + kb + ak1 * 8);
        cp16(Bs + (uint32_t)(br * 80 + bk * 16),
             g_Bext + (size_t)(n0 + br) * K_EXT + kb + bk * 8);
        cp_commit();
    };

    float acc[2][8][4];
#pragma unroll
    for (int i = 0; i < 2; i++)
#pragma unroll
        for (int j = 0; j < 8; j++)
#pragma unroll
            for (int q = 0; q < 4; q++) acc[i][j][q] = 0.0f;

    issue_stage(0, 0);
    issue_stage(1, 1);

    // ldmatrix address components (fixed per thread)
    const int a_row = (lane & 15);          // row within m16 tile
    const int a_chk = (lane >> 4);          // 0/1 -> k8 halves
    const int b_row = ((lane >> 4) << 3) + (lane & 7);  // row within n16 pair
    const int b_chk = (lane >> 3) & 1;

    for (int it = 0; it < ITERS; ++it) {
        if (it + 2 < ITERS) { cp_wait<1>(); } else { cp_wait<0>(); }
        __syncthreads();
        if (it + 2 < ITERS) issue_stage(it + 2, (it + 2) % NSTAGE);

        const uint32_t As = sbase + (uint32_t)(it % NSTAGE) * STAGE_BYTES;
        const uint32_t Bs = As + A_BYTES;

#pragma unroll
        for (int kk = 0; kk < 2; ++kk) {          // two k16 steps per BK=32
            const int kb = kk * 16;
            uint32_t a[2][4];
#pragma unroll
            for (int am = 0; am < 2; ++am) {
                uint32_t addr = As +
                    (uint32_t)((m_warp + am * 16 + a_row) * 80 + kb * 2 + a_chk * 16);
                ldm_x4(a[am][0], a[am][1], a[am][2], a[am][3], addr);
            }
            uint32_t b[4][4];
#pragma unroll
            for (int bn = 0; bn < 4; ++bn) {      // each covers two n8 tiles
                uint32_t addr = Bs +
                    (uint32_t)((n_warp + bn * 16 + b_row) * 80 + kb * 2 + b_chk * 16);
                ldm_x4(b[bn][0], b[bn][1], b[bn][2], b[bn][3], addr);
            }
#pragma unroll
            for (int am = 0; am < 2; ++am)
#pragma unroll
                for (int j = 0; j < 8; ++j)
                    mma_bf16(acc[am][j], a[am], b[j >> 1][(j & 1) * 2],
                             b[j >> 1][(j & 1) * 2 + 1]);
        }
        __syncthreads();
    }

    // write accumulators to gates scratch
    const int r_base = lane >> 2;
    const int c_base = (lane & 3) * 2;
#pragma unroll
    for (int am = 0; am < 2; ++am) {
#pragma unroll
        for (int j = 0; j < 8; ++j) {
            int col = n0 + n_warp + j * 8 + c_base;
            int row0 = m0 + m_warp + am * 16 + r_base;
            *(float2*)(g_gates + (size_t)row0 * N_TOT + col) =
                make_float2(acc[am][j][0], acc[am][j][1]);
            *(float2*)(g_gates + (size_t)(row0 + 8) * N_TOT + col) =
                make_float2(acc[am][j][2], acc[am][j][3]);
        }
    }
}

// ---------------------------------------------------------------------------
// LSTM epilogue: one block per batch row
// ---------------------------------------------------------------------------
__device__ __forceinline__ float sigmoidf_(float x) { return 1.0f / (1.0f + __expf(-x)); }

__device__ __forceinline__ void block_ln_stats(float s, float ss, float* shm,
                                               float& mean, float& rstd)
{
    const int lane = threadIdx.x & 31;
    const int warp = threadIdx.x >> 5;
#pragma unroll
    for (int o = 16; o > 0; o >>= 1) {
        s  += __shfl_xor_sync(0xffffffff, s,  o);
        ss += __shfl_xor_sync(0xffffffff, ss, o);
    }
    if (lane == 0) { shm[warp] = s; shm[8 + warp] = ss; }
    __syncthreads();
    if (threadIdx.x == 0) {
        float ts = 0.f, tss = 0.f;
#pragma unroll
        for (int i = 0; i < 8; i++) { ts += shm[i]; tss += shm[8 + i]; }
        shm[16] = ts; shm[17] = tss;
    }
    __syncthreads();
    const float ts = shm[16], tss = shm[17];
    mean = ts * (1.0f / 1024.0f);
    float var = tss * (1.0f / 1024.0f) - mean * mean;
    rstd = rsqrtf(var + 1e-5f);
    __syncthreads();
}

__global__ __launch_bounds__(256) void lstm_epilogue_kernel(
    const float* __restrict__ cx,
    const float* __restrict__ bias_ih, const float* __restrict__ bias_hh,
    const float* __restrict__ ln_i_g,  const float* __restrict__ ln_i_b,
    const float* __restrict__ ln_f_g,  const float* __restrict__ ln_f_b,
    const float* __restrict__ ln_c_g,  const float* __restrict__ ln_c_b,
    const float* __restrict__ ln_cy_g, const float* __restrict__ ln_cy_b,
    const float* __restrict__ ln_o_g,  const float* __restrict__ ln_o_b,
    float* __restrict__ hy_out, float* __restrict__ cy_out)
{
    __shared__ float shm[18];
    const int b   = blockIdx.x;
    const int tid = threadIdx.x;
    const int h4  = tid * 4;

    const float* grow = g_gates + (size_t)b * N_TOT;

    float4 gv[4];
#pragma unroll
    for (int q = 0; q < 4; q++) {
        const int col = q * H_SZ + h4;
        float4 v  = *(const float4*)(grow + col);
        float4 bi = *(const float4*)(bias_ih + col);
        float4 bh = *(const float4*)(bias_hh + col);
        v.x += bi.x + bh.x; v.y += bi.y + bh.y;
        v.z += bi.z + bh.z; v.w += bi.w + bh.w;
        gv[q] = v;
    }

    const float* gam[4] = { ln_i_g, ln_f_g, ln_c_g, ln_o_g };
    const float* bet[4] = { ln_i_b, ln_f_b, ln_c_b, ln_o_b };
    float4 act[4];
#pragma unroll
    for (int q = 0; q < 4; q++) {
        float4 v = gv[q];
        float s  = v.x + v.y + v.z + v.w;
        float ss = v.x * v.x + v.y * v.y + v.z * v.z + v.w * v.w;
        float mean, rstd;
        block_ln_stats(s, ss, shm, mean, rstd);
        float4 g4 = *(const float4*)(gam[q] + h4);
        float4 b4 = *(const float4*)(bet[q] + h4);
        float4 n;
        n.x = (v.x - mean) * rstd * g4.x + b4.x;
        n.y = (v.y - mean) * rstd * g4.y + b4.y;
        n.z = (v.z - mean) * rstd * g4.z + b4.z;
        n.w = (v.w - mean) * rstd * g4.w + b4.w;
        if (q == 2) {
            n.x = tanhf(n.x); n.y = tanhf(n.y); n.z = tanhf(n.z); n.w = tanhf(n.w);
        } else {
            n.x = sigmoidf_(n.x); n.y = sigmoidf_(n.y);
            n.z = sigmoidf_(n.z); n.w = sigmoidf_(n.w);
        }
        act[q] = n;
    }

    float4 cxv = *(const float4*)(cx + (size_t)b * H_SZ + h4);
    float4 t;
    t.x = act[1].x * cxv.x + act[0].x * act[2].x;
    t.y = act[1].y * cxv.y + act[0].y * act[2].y;
    t.z = act[1].z * cxv.z + act[0].z * act[2].z;
    t.w = act[1].w * cxv.w + act[0].w * act[2].w;

    {
        float s  = t.x + t.y + t.z + t.w;
        float ss = t.x * t.x + t.y * t.y + t.z * t.z + t.w * t.w;
        float mean, rstd;
        block_ln_stats(s, ss, shm, mean, rstd);
        float4 g4 = *(const float4*)(ln_cy_g + h4);
        float4 b4 = *(const float4*)(ln_cy_b + h4);
        float4 cyv;
        cyv.x = (t.x - mean) * rstd * g4.x + b4.x;
        cyv.y = (t.y - mean) * rstd * g4.y + b4.y;
        cyv.z = (t.z - mean) * rstd * g4.z + b4.z;
        cyv.w = (t.w - mean) * rstd * g4.w + b4.w;

        float4 hyv;
        hyv.x = act[3].x * tanhf(cyv.x);
        hyv.y = act[3].y * tanhf(cyv.y);
        hyv.z = act[3].z * tanhf(cyv.z);
        hyv.w = act[3].w * tanhf(cyv.w);

        *(float4*)(cy_out + (size_t)b * H_SZ + h4) = cyv;
        *(float4*)(hy_out + (size_t)b * H_SZ + h4) = hyv;
    }
}

// ---------------------------------------------------------------------------
// Launch
// ---------------------------------------------------------------------------
extern "C" void kernel_launch(void* const* d_in, const int* in_sizes, int n_in,
                              void* d_out, int out_size)
{
    const float* x        = (const float*)d_in[0];
    const float* hx       = (const float*)d_in[1];
    const float* cx       = (const float*)d_in[2];
    const float* wih      = (const float*)d_in[3];
    const float* whh      = (const float*)d_in[4];
    const float* bias_ih  = (const float*)d_in[5];
    const float* bias_hh  = (const float*)d_in[6];
    const float* ln_i_g   = (const float*)d_in[7];
    const float* ln_i_b   = (const float*)d_in[8];
    const float* ln_f_g   = (const float*)d_in[9];
    const float* ln_f_b   = (const float*)d_in[10];
    const float* ln_c_g   = (const float*)d_in[11];
    const float* ln_c_b   = (const float*)d_in[12];
    const float* ln_cy_g  = (const float*)d_in[13];
    const float* ln_cy_b  = (const float*)d_in[14];
    const float* ln_o_g   = (const float*)d_in[15];
    const float* ln_o_b   = (const float*)d_in[16];

    float* out = (float*)d_out;
    float* hy  = out;
    float* cy  = out + (size_t)B_SZ * H_SZ;

    static bool attr_set = false;
    if (!attr_set) {
        cudaFuncSetAttribute(gemm_mma_kernel,
                             cudaFuncAttributeMaxDynamicSharedMemorySize, GEMM_SMEM);
        attr_set = true;
    }

    convert_A_kernel<<<(B_SZ * K_TOT / 4) / 256, 256>>>(x, hx);
    convert_B_kernel<<<(N_TOT * K_TOT / 4) / 256, 256>>>(wih, whh);

    dim3 ggrid(N_TOT / BN, B_SZ / BM);   // (32, 32)
    gemm_mma_kernel<<<ggrid, 512, GEMM_SMEM>>>();

    lstm_epilogue_kernel<<<B_SZ, 256>>>(cx, bias_ih, bias_hh,
                                        ln_i_g, ln_i_b, ln_f_g, ln_f_b,
                                        ln_c_g, ln_c_b, ln_cy_g, ln_cy_b,
                                        ln_o_g, ln_o_b, hy, cy);
}

// round 5
// speedup vs baseline: 2.3059x; 1.1633x over previous
#include <cuda_runtime.h>
#include <cuda_bf16.h>
#include <cstdint>

// ---------------------------------------------------------------------------
// Problem constants
// ---------------------------------------------------------------------------
#define B_SZ 8192
#define H_SZ 1024
#define K_TOT 2048       // 1024 (x/Wih) + 1024 (hx/Whh)
#define N_TOT 4096       // 4 gates * H
#define K_EXT 6144       // 3 * K_TOT (hi*hi | lo*hi | hi*lo split-GEMM)

// GEMM tiling
#define BM 256
#define BN 128
#define BK 32
#define ITERS (K_EXT / BK)    // 192
#define NSTAGE 4

// smem: padded rows of 40 bf16 (80 B) for conflict-free ldmatrix
#define ROW_PITCH 40
#define A_BYTES (BM * ROW_PITCH * 2)   // 20480
#define B_BYTES (BN * ROW_PITCH * 2)   // 10240
#define STAGE_BYTES (A_BYTES + B_BYTES)          // 30720
#define GEMM_SMEM (NSTAGE * STAGE_BYTES)         // 122880

// ---------------------------------------------------------------------------
// Scratch (device globals; no allocations allowed)
// ---------------------------------------------------------------------------
__device__ __nv_bfloat16 g_Aext[(size_t)B_SZ * K_EXT];   // [Ahi | Alo | Ahi]
__device__ __nv_bfloat16 g_Bext[(size_t)N_TOT * K_EXT];  // [Bhi | Bhi | Blo]
__device__ float         g_gates[(size_t)B_SZ * N_TOT];

// ---------------------------------------------------------------------------
// PTX helpers (sm_100 base ISA only: cp.async / ldmatrix / mma.sync)
// ---------------------------------------------------------------------------
__device__ __forceinline__ uint32_t smem_u32(const void* p) {
    uint32_t r;
    asm("{ .reg .u64 t; cvta.to.shared.u64 t, %1; cvt.u32.u64 %0, t; }"
        : "=r"(r) : "l"(p));
    return r;
}
__device__ __forceinline__ void cp16(uint32_t dst, const void* src) {
    asm volatile("cp.async.cg.shared.global [%0], [%1], 16;" :: "r"(dst), "l"(src));
}
__device__ __forceinline__ void cp_commit() {
    asm volatile("cp.async.commit_group;" ::: "memory");
}
template <int N> __device__ __forceinline__ void cp_wait() {
    asm volatile("cp.async.wait_group %0;" :: "n"(N) : "memory");
}
__device__ __forceinline__ void ldm_x4(uint32_t& r0, uint32_t& r1,
                                       uint32_t& r2, uint32_t& r3, uint32_t addr) {
    asm volatile("ldmatrix.sync.aligned.m8n8.x4.shared.b16 {%0,%1,%2,%3}, [%4];"
                 : "=r"(r0), "=r"(r1), "=r"(r2), "=r"(r3) : "r"(addr));
}
__device__ __forceinline__ void mma_bf16(float* c, const uint32_t* a,
                                         uint32_t b0, uint32_t b1) {
    asm volatile(
        "mma.sync.aligned.m16n8k16.row.col.f32.bf16.bf16.f32 "
        "{%0,%1,%2,%3}, {%4,%5,%6,%7}, {%8,%9}, {%0,%1,%2,%3};"
        : "+f"(c[0]), "+f"(c[1]), "+f"(c[2]), "+f"(c[3])
        : "r"(a[0]), "r"(a[1]), "r"(a[2]), "r"(a[3]), "r"(b0), "r"(b1));
}

// ---------------------------------------------------------------------------
// Conversion: fp32 -> bf16 hi/lo extended-K scratch
// A = [x|hx] rows 8192, K=2048; A_ext row = [hi | lo | hi]
// B = [Wih|Whh] rows 4096;      B_ext row = [hi | hi | lo]
// ---------------------------------------------------------------------------
__device__ __forceinline__ void split4(const float4& v, __nv_bfloat162& h01,
                                       __nv_bfloat162& h23, __nv_bfloat162& l01,
                                       __nv_bfloat162& l23) {
    float vv[4] = {v.x, v.y, v.z, v.w};
    __nv_bfloat16 h[4], l[4];
#pragma unroll
    for (int j = 0; j < 4; j++) {
        h[j] = __float2bfloat16_rn(vv[j]);
        l[j] = __float2bfloat16_rn(vv[j] - __bfloat162float(h[j]));
    }
    h01 = __halves2bfloat162(h[0], h[1]);
    h23 = __halves2bfloat162(h[2], h[3]);
    l01 = __halves2bfloat162(l[0], l[1]);
    l23 = __halves2bfloat162(l[2], l[3]);
}

__global__ __launch_bounds__(256) void convert_A_kernel(
    const float* __restrict__ x, const float* __restrict__ hx)
{
    int idx = blockIdx.x * 256 + threadIdx.x;      // one float4 per thread
    int row = idx >> 9;                            // 512 float4 per K_TOT row
    int c4  = (idx & 511) * 4;
    const float* src = (c4 < H_SZ) ? (x  + (size_t)row * H_SZ + c4)
                                   : (hx + (size_t)row * H_SZ + (c4 - H_SZ));
    float4 v = *(const float4*)src;
    __nv_bfloat162 h01, h23, l01, l23;
    split4(v, h01, h23, l01, l23);
    __nv_bfloat16* dst = g_Aext + (size_t)row * K_EXT;
    *(__nv_bfloat162*)(dst + c4)              = h01;
    *(__nv_bfloat162*)(dst + c4 + 2)          = h23;
    *(__nv_bfloat162*)(dst + K_TOT + c4)      = l01;   // seg1: Alo
    *(__nv_bfloat162*)(dst + K_TOT + c4 + 2)  = l23;
    *(__nv_bfloat162*)(dst + 2*K_TOT + c4)    = h01;   // seg2: Ahi
    *(__nv_bfloat162*)(dst + 2*K_TOT + c4 + 2)= h23;
}

__global__ __launch_bounds__(256) void convert_B_kernel(
    const float* __restrict__ wih, const float* __restrict__ whh)
{
    int idx = blockIdx.x * 256 + threadIdx.x;
    int row = idx >> 9;
    int c4  = (idx & 511) * 4;
    const float* src = (c4 < H_SZ) ? (wih + (size_t)row * H_SZ + c4)
                                   : (whh + (size_t)row * H_SZ + (c4 - H_SZ));
    float4 v = *(const float4*)src;
    __nv_bfloat162 h01, h23, l01, l23;
    split4(v, h01, h23, l01, l23);
    __nv_bfloat16* dst = g_Bext + (size_t)row * K_EXT;
    *(__nv_bfloat162*)(dst + c4)              = h01;
    *(__nv_bfloat162*)(dst + c4 + 2)          = h23;
    *(__nv_bfloat162*)(dst + K_TOT + c4)      = h01;   // seg1: Bhi
    *(__nv_bfloat162*)(dst + K_TOT + c4 + 2)  = h23;
    *(__nv_bfloat162*)(dst + 2*K_TOT + c4)    = l01;   // seg2: Blo
    *(__nv_bfloat162*)(dst + 2*K_TOT + c4 + 2)= l23;
}

// ---------------------------------------------------------------------------
// GEMM: gates[8192,4096] = A_ext[8192,6144] @ B_ext[4096,6144]^T  (bf16 mma.sync)
// CTA 256x128, BK=32, 512 threads (16 warps, 8x2), warp tile 32x64.
// 4-stage cp.async pipeline, ONE barrier per iteration, frag preloading.
// ---------------------------------------------------------------------------
__global__ __launch_bounds__(512, 1) void gemm_mma_kernel()
{
    extern __shared__ char smem[];
    const uint32_t sbase = smem_u32(smem);

    const int tid  = threadIdx.x;
    const int lane = tid & 31;
    const int wid  = tid >> 5;
    const int m_warp = (wid >> 1) * 32;
    const int n_warp = (wid & 1) * 64;

    const int m0 = blockIdx.y * BM;
    const int n0 = blockIdx.x * BN;

    // global-load indexing (16B chunks; smem row pitch = 80 B)
    const int ac0 = tid * 2, ac1 = tid * 2 + 1;
    const int ar0 = ac0 >> 2, ak0 = ac0 & 3;
    const int ar1 = ac1 >> 2, ak1 = ac1 & 3;
    const int br  = tid >> 2, bk = tid & 3;

    const __nv_bfloat16* gA0 = g_Aext + (size_t)(m0 + ar0) * K_EXT + ak0 * 8;
    const __nv_bfloat16* gA1 = g_Aext + (size_t)(m0 + ar1) * K_EXT + ak1 * 8;
    const __nv_bfloat16* gB  = g_Bext + (size_t)(n0 + br)  * K_EXT + bk  * 8;
    const uint32_t sA0 = (uint32_t)(ar0 * 80 + ak0 * 16);
    const uint32_t sA1 = (uint32_t)(ar1 * 80 + ak1 * 16);
    const uint32_t sB  = (uint32_t)(br * 80 + bk * 16) + A_BYTES;

    auto issue_stage = [&](int it) {
        const uint32_t stb = sbase + (uint32_t)(it & (NSTAGE - 1)) * STAGE_BYTES;
        const int kb = it * BK;
        cp16(stb + sA0, gA0 + kb);
        cp16(stb + sA1, gA1 + kb);
        cp16(stb + sB,  gB  + kb);
        cp_commit();
    };

    float acc[2][8][4];
#pragma unroll
    for (int i = 0; i < 2; i++)
#pragma unroll
        for (int j = 0; j < 8; j++)
#pragma unroll
            for (int q = 0; q < 4; q++) acc[i][j][q] = 0.0f;

    issue_stage(0);
    issue_stage(1);
    issue_stage(2);

    // ldmatrix address components (fixed per thread)
    const int a_row = (lane & 15);
    const int a_chk = (lane >> 4);
    const int b_row = ((lane >> 4) << 3) + (lane & 7);
    const int b_chk = (lane >> 3) & 1;

    const uint32_t aoff = (uint32_t)((m_warp + a_row) * 80 + a_chk * 16);
    const uint32_t boff = (uint32_t)((n_warp + b_row) * 80 + b_chk * 16) + A_BYTES;

    for (int it = 0; it < ITERS; ++it) {
        cp_wait<NSTAGE - 2>();        // stage `it` data arrived (FIXED: call!)
        __syncthreads();              // whole tile arrived; slot (it+3)&3 is free
        if (it + 3 < ITERS) issue_stage(it + 3);
        else cp_commit();             // keep group counting aligned for cp_wait

        const uint32_t stb = sbase + (uint32_t)(it & (NSTAGE - 1)) * STAGE_BYTES;

        uint32_t a[2][4], b0[4][4], b1[4][4];
        // A frags, k-step 0
#pragma unroll
        for (int am = 0; am < 2; ++am)
            ldm_x4(a[am][0], a[am][1], a[am][2], a[am][3],
                   stb + aoff + (uint32_t)(am * 16 * 80));
        // B frags, both k-steps (preload → ILP across the MMA burst)
#pragma unroll
        for (int bn = 0; bn < 4; ++bn)
            ldm_x4(b0[bn][0], b0[bn][1], b0[bn][2], b0[bn][3],
                   stb + boff + (uint32_t)(bn * 16 * 80));
#pragma unroll
        for (int bn = 0; bn < 4; ++bn)
            ldm_x4(b1[bn][0], b1[bn][1], b1[bn][2], b1[bn][3],
                   stb + boff + (uint32_t)(bn * 16 * 80 + 32));
        // MMA burst, k-step 0
#pragma unroll
        for (int am = 0; am < 2; ++am)
#pragma unroll
            for (int j = 0; j < 8; ++j)
                mma_bf16(acc[am][j], a[am], b0[j >> 1][(j & 1) * 2],
                         b0[j >> 1][(j & 1) * 2 + 1]);
        // A frags, k-step 1 (reuse regs; WAR resolved after burst)
#pragma unroll
        for (int am = 0; am < 2; ++am)
            ldm_x4(a[am][0], a[am][1], a[am][2], a[am][3],
                   stb + aoff + (uint32_t)(am * 16 * 80 + 32));
        // MMA burst, k-step 1
#pragma unroll
        for (int am = 0; am < 2; ++am)
#pragma unroll
            for (int j = 0; j < 8; ++j)
                mma_bf16(acc[am][j], a[am], b1[j >> 1][(j & 1) * 2],
                         b1[j >> 1][(j & 1) * 2 + 1]);
    }

    // write accumulators to gates scratch
    const int r_base = lane >> 2;
    const int c_base = (lane & 3) * 2;
#pragma unroll
    for (int am = 0; am < 2; ++am) {
#pragma unroll
        for (int j = 0; j < 8; ++j) {
            int col = n0 + n_warp + j * 8 + c_base;
            int row0 = m0 + m_warp + am * 16 + r_base;
            *(float2*)(g_gates + (size_t)row0 * N_TOT + col) =
                make_float2(acc[am][j][0], acc[am][j][1]);
            *(float2*)(g_gates + (size_t)(row0 + 8) * N_TOT + col) =
                make_float2(acc[am][j][2], acc[am][j][3]);
        }
    }
}

// ---------------------------------------------------------------------------
// LSTM epilogue: one block per batch row
// ---------------------------------------------------------------------------
__device__ __forceinline__ float sigmoidf_(float x) { return 1.0f / (1.0f + __expf(-x)); }

__device__ __forceinline__ void block_ln_stats(float s, float ss, float* shm,
                                               float& mean, float& rstd)
{
    const int lane = threadIdx.x & 31;
    const int warp = threadIdx.x >> 5;
#pragma unroll
    for (int o = 16; o > 0; o >>= 1) {
        s  += __shfl_xor_sync(0xffffffff, s,  o);
        ss += __shfl_xor_sync(0xffffffff, ss, o);
    }
    if (lane == 0) { shm[warp] = s; shm[8 + warp] = ss; }
    __syncthreads();
    if (threadIdx.x == 0) {
        float ts = 0.f, tss = 0.f;
#pragma unroll
        for (int i = 0; i < 8; i++) { ts += shm[i]; tss += shm[8 + i]; }
        shm[16] = ts; shm[17] = tss;
    }
    __syncthreads();
    const float ts = shm[16], tss = shm[17];
    mean = ts * (1.0f / 1024.0f);
    float var = tss * (1.0f / 1024.0f) - mean * mean;
    rstd = rsqrtf(var + 1e-5f);
    __syncthreads();
}

__global__ __launch_bounds__(256) void lstm_epilogue_kernel(
    const float* __restrict__ cx,
    const float* __restrict__ bias_ih, const float* __restrict__ bias_hh,
    const float* __restrict__ ln_i_g,  const float* __restrict__ ln_i_b,
    const float* __restrict__ ln_f_g,  const float* __restrict__ ln_f_b,
    const float* __restrict__ ln_c_g,  const float* __restrict__ ln_c_b,
    const float* __restrict__ ln_cy_g, const float* __restrict__ ln_cy_b,
    const float* __restrict__ ln_o_g,  const float* __restrict__ ln_o_b,
    float* __restrict__ hy_out, float* __restrict__ cy_out)
{
    __shared__ float shm[18];
    const int b   = blockIdx.x;
    const int tid = threadIdx.x;
    const int h4  = tid * 4;

    const float* grow = g_gates + (size_t)b * N_TOT;

    float4 gv[4];
#pragma unroll
    for (int q = 0; q < 4; q++) {
        const int col = q * H_SZ + h4;
        float4 v  = *(const float4*)(grow + col);
        float4 bi = *(const float4*)(bias_ih + col);
        float4 bh = *(const float4*)(bias_hh + col);
        v.x += bi.x + bh.x; v.y += bi.y + bh.y;
        v.z += bi.z + bh.z; v.w += bi.w + bh.w;
        gv[q] = v;
    }

    const float* gam[4] = { ln_i_g, ln_f_g, ln_c_g, ln_o_g };
    const float* bet[4] = { ln_i_b, ln_f_b, ln_c_b, ln_o_b };
    float4 act[4];
#pragma unroll
    for (int q = 0; q < 4; q++) {
        float4 v = gv[q];
        float s  = v.x + v.y + v.z + v.w;
        float ss = v.x * v.x + v.y * v.y + v.z * v.z + v.w * v.w;
        float mean, rstd;
        block_ln_stats(s, ss, shm, mean, rstd);
        float4 g4 = *(const float4*)(gam[q] + h4);
        float4 b4 = *(const float4*)(bet[q] + h4);
        float4 n;
        n.x = (v.x - mean) * rstd * g4.x + b4.x;
        n.y = (v.y - mean) * rstd * g4.y + b4.y;
        n.z = (v.z - mean) * rstd * g4.z + b4.z;
        n.w = (v.w - mean) * rstd * g4.w + b4.w;
        if (q == 2) {
            n.x = tanhf(n.x); n.y = tanhf(n.y); n.z = tanhf(n.z); n.w = tanhf(n.w);
        } else {
            n.x = sigmoidf_(n.x); n.y = sigmoidf_(n.y);
            n.z = sigmoidf_(n.z); n.w = sigmoidf_(n.w);
        }
        act[q] = n;
    }

    float4 cxv = *(const float4*)(cx + (size_t)b * H_SZ + h4);
    float4 t;
    t.x = act[1].x * cxv.x + act[0].x * act[2].x;
    t.y = act[1].y * cxv.y + act[0].y * act[2].y;
    t.z = act[1].z * cxv.z + act[0].z * act[2].z;
    t.w = act[1].w * cxv.w + act[0].w * act[2].w;

    {
        float s  = t.x + t.y + t.z + t.w;
        float ss = t.x * t.x + t.y * t.y + t.z * t.z + t.w * t.w;
        float mean, rstd;
        block_ln_stats(s, ss, shm, mean, rstd);
        float4 g4 = *(const float4*)(ln_cy_g + h4);
        float4 b4 = *(const float4*)(ln_cy_b + h4);
        float4 cyv;
        cyv.x = (t.x - mean) * rstd * g4.x + b4.x;
        cyv.y = (t.y - mean) * rstd * g4.y + b4.y;
        cyv.z = (t.z - mean) * rstd * g4.z + b4.z;
        cyv.w = (t.w - mean) * rstd * g4.w + b4.w;

        float4 hyv;
        hyv.x = act[3].x * tanhf(cyv.x);
        hyv.y = act[3].y * tanhf(cyv.y);
        hyv.z = act[3].z * tanhf(cyv.z);
        hyv.w = act[3].w * tanhf(cyv.w);

        *(float4*)(cy_out + (size_t)b * H_SZ + h4) = cyv;
        *(float4*)(hy_out + (size_t)b * H_SZ + h4) = hyv;
    }
}

// ---------------------------------------------------------------------------
// Launch
// ---------------------------------------------------------------------------
extern "C" void kernel_launch(void* const* d_in, const int* in_sizes, int n_in,
                              void* d_out, int out_size)
{
    const float* x        = (const float*)d_in[0];
    const float* hx       = (const float*)d_in[1];
    const float* cx       = (const float*)d_in[2];
    const float* wih      = (const float*)d_in[3];
    const float* whh      = (const float*)d_in[4];
    const float* bias_ih  = (const float*)d_in[5];
    const float* bias_hh  = (const float*)d_in[6];
    const float* ln_i_g   = (const float*)d_in[7];
    const float* ln_i_b   = (const float*)d_in[8];
    const float* ln_f_g   = (const float*)d_in[9];
    const float* ln_f_b   = (const float*)d_in[10];
    const float* ln_c_g   = (const float*)d_in[11];
    const float* ln_c_b   = (const float*)d_in[12];
    const float* ln_cy_g  = (const float*)d_in[13];
    const float* ln_cy_b  = (const float*)d_in[14];
    const float* ln_o_g   = (const float*)d_in[15];
    const float* ln_o_b   = (const float*)d_in[16];

    float* out = (float*)d_out;
    float* hy  = out;
    float* cy  = out + (size_t)B_SZ * H_SZ;

    static bool attr_set = false;
    if (!attr_set) {
        cudaFuncSetAttribute(gemm_mma_kernel,
                             cudaFuncAttributeMaxDynamicSharedMemorySize, GEMM_SMEM);
        attr_set = true;
    }

    convert_A_kernel<<<(B_SZ * K_TOT / 4) / 256, 256>>>(x, hx);
    convert_B_kernel<<<(N_TOT * K_TOT / 4) / 256, 256>>>(wih, whh);

    dim3 ggrid(N_TOT / BN, B_SZ / BM);   // (32, 32)
    gemm_mma_kernel<<<ggrid, 512, GEMM_SMEM>>>();

    lstm_epilogue_kernel<<<B_SZ, 256>>>(cx, bias_ih, bias_hh,
                                        ln_i_g, ln_i_b, ln_f_g, ln_f_b,
                                        ln_c_g, ln_c_b, ln_cy_g, ln_cy_b,
                                        ln_o_g, ln_o_b, hy, cy);
}